// round 9
// baseline (speedup 1.0000x reference)
#include <cuda_runtime.h>
#include <math.h>

#define T_  1024
#define B_  2
#define E_  1024
#define H_  16
#define D_  64
#define TB_ 2048
#define RB_ 4094

// ---------------- scratch (hi/lo interleaved buffers use *_s suffix) -----------
__device__ float g_Wins [3 * E_ * E_ * 2];
__device__ float g_Wposs[E_ * E_ * 2];
__device__ float g_Wouts[E_ * E_ * 2];
__device__ float g_bin [3 * E_];
__device__ float g_bpos[E_];
__device__ float g_bout[E_];
__device__ float g_rw  [E_];
__device__ float g_rr  [E_];
__device__ float g_ins [TB_ * E_ * 2];    // input split
__device__ float g_poss[RB_ * E_ * 2];    // pos split
__device__ float g_qws [TB_ * E_ * 2];    // (q + rw) split
__device__ float g_qrs [TB_ * E_ * 2];    // (q + rr) split
__device__ float g_kvs [TB_ * 4096];      // k split [0,2048) | v split [2048,4096)
__device__ float g_rs  [RB_ * E_ * 2];    // r split
__device__ float g_atts[TB_ * E_ * 2];    // attention out split

// ---------------- tf32 helpers ----------------
__device__ __forceinline__ unsigned f2tf(float f) {
    unsigned r; asm("cvt.rna.tf32.f32 %0, %1;" : "=r"(r) : "f"(f)); return r;
}
__device__ __forceinline__ void split2(float v, float& hi, float& lo) {
    hi = __uint_as_float(f2tf(v));
    lo = __uint_as_float(f2tf(v - hi));
}
__device__ __forceinline__ float4 splitpk(float a, float b) {
    float h0, l0, h1, l1;
    split2(a, h0, l0); split2(b, h1, l1);
    return make_float4(h0, l0, h1, l1);
}
__device__ __forceinline__ void mma8(float* c, const float* a, const float* b) {
    asm volatile("mma.sync.aligned.m16n8k8.row.col.f32.tf32.tf32.f32 "
                 "{%0,%1,%2,%3},{%4,%5,%6,%7},{%8,%9},{%0,%1,%2,%3};"
                 : "+f"(c[0]), "+f"(c[1]), "+f"(c[2]), "+f"(c[3])
                 : "r"(__float_as_uint(a[0])), "r"(__float_as_uint(a[1])),
                   "r"(__float_as_uint(a[2])), "r"(__float_as_uint(a[3])),
                   "r"(__float_as_uint(b[0])), "r"(__float_as_uint(b[1])));
}
__device__ __forceinline__ void mma3(float* c, const float* ah, const float* al,
                                     const float* bh, const float* bl) {
    mma8(c, ah, bh);
    mma8(c, ah, bl);
    mma8(c, al, bh);
}

// ---------------- hypernet: weights written SPLIT, biases fp32 -----------------
#define HN0 3145728
#define HN1 (HN0 + 1048576)
#define HN2 (HN1 + 1048576)
#define HN3 (HN2 + 3072)
#define HN4 (HN3 + 1024)
#define HN5 (HN4 + 1024)
#define HN6 (HN5 + 1024)
#define HN7 (HN6 + 1024)

__global__ __launch_bounds__(256) void hyper_all(
    const float* __restrict__ w_in,  const float* __restrict__ w_pos,
    const float* __restrict__ w_out, const float* __restrict__ b_in,
    const float* __restrict__ b_pos, const float* __restrict__ b_out,
    const float* __restrict__ rwb,   const float* __restrict__ rrb,
    const float* __restrict__ f,
    float* __restrict__ oWin,  float* __restrict__ oWpos,
    float* __restrict__ oWout, float* __restrict__ obin,
    float* __restrict__ obpos, float* __restrict__ obout,
    float* __restrict__ orw,   float* __restrict__ orr)
{
    int idx = blockIdx.x * blockDim.x + threadIdx.x;
    if (idx >= HN7) return;
    const float* src; float* dst; int off; int spl = 0;
    if      (idx < HN0) { src = w_in;  dst = oWin;  off = idx;       spl = 1; }
    else if (idx < HN1) { src = w_pos; dst = oWpos; off = idx - HN0; spl = 1; }
    else if (idx < HN2) { src = w_out; dst = oWout; off = idx - HN1; spl = 1; }
    else if (idx < HN3) { src = b_in;  dst = obin;  off = idx - HN2; }
    else if (idx < HN4) { src = b_pos; dst = obpos; off = idx - HN3; }
    else if (idx < HN5) { src = b_out; dst = obout; off = idx - HN4; }
    else if (idx < HN6) { src = rwb;   dst = orw;   off = idx - HN5; }
    else                { src = rrb;   dst = orr;   off = idx - HN6; }
    const float4* wp = (const float4*)(src + (size_t)off * 8);
    float4 a = wp[0], b = wp[1];
    float4 f0 = *(const float4*)f;
    float4 f1 = *(const float4*)(f + 4);
    float v = a.x*f0.x + a.y*f0.y + a.z*f0.z + a.w*f0.w
            + b.x*f1.x + b.y*f1.y + b.z*f1.z + b.w*f1.w;
    if (spl) {
        float hi, lo; split2(v, hi, lo);
        dst[2 * (size_t)off] = hi;
        dst[2 * (size_t)off + 1] = lo;
    } else {
        dst[off] = v;
    }
}

// ---------------- split input & pos into interleaved hi/lo ---------------------
#define NIN4 (TB_ * E_ / 4)
#define NPOS4 (RB_ * E_ / 4)
__global__ __launch_bounds__(256) void split_inputs(const float* __restrict__ input,
                                                    const float* __restrict__ pos,
                                                    float* __restrict__ ins,
                                                    float* __restrict__ poss)
{
    int i4 = blockIdx.x * blockDim.x + threadIdx.x;
    const float* src; float* dst; int off;
    if (i4 < NIN4) { src = input; dst = ins; off = i4; }
    else if (i4 < NIN4 + NPOS4) { src = pos; dst = poss; off = i4 - NIN4; }
    else return;
    float4 v = *(const float4*)(src + (size_t)off * 4);
    *(float4*)(dst + (size_t)off * 8)     = splitpk(v.x, v.y);
    *(float4*)(dst + (size_t)off * 8 + 4) = splitpk(v.z, v.w);
}

// ---------------- 3xtf32 NT GEMM on pre-split operands -------------------------
// As[m][2K], Bs[n][2K] hi/lo interleaved. smem rows stride 72 (32k*2 + 8 pad).
// modes: 0 -> o0 = fp32 C (stride N), bias added
//        1 -> o0 = split C (stride 2N), bias added
//        2 -> qkv: n<E: (acc+bias+rw)->o0 split, (acc+bias+rr)->o1 split (stride 2E)
//                  n>=E: (acc+bias)->o2 split at (n-E)*2 (stride 4096)
__global__ __launch_bounds__(256) void gemm3s(const float* __restrict__ As,
                                              const float* __restrict__ Bs,
                                              const float* __restrict__ bias,
                                              float* __restrict__ o0,
                                              float* __restrict__ o1,
                                              float* __restrict__ o2,
                                              const float* __restrict__ rwv,
                                              const float* __restrict__ rrv,
                                              int M, int N, int K, int mode)
{
    __shared__ float sm[18432];
    int bm = blockIdx.y * 128, bn = blockIdx.x * 128;
    int tid = threadIdx.x;
    int w = tid >> 5, lane = tid & 31;
    int g = lane >> 2, tg = lane & 3;
    int wm = w & 1, wn = w >> 1;
    float acc[4][4][4] = {};

    for (int k0 = 0; k0 < K; k0 += 32) {
#pragma unroll
        for (int it = 0; it < 8; it++) {
            int t = tid + 256 * it;
            int row = t >> 4, q4 = (t & 15) << 2;
            int m = bm + row;
            float4 av = (m < M) ? *(const float4*)(As + (size_t)m * 2 * K + k0 * 2 + q4)
                                : make_float4(0.f, 0.f, 0.f, 0.f);
            *(float4*)&sm[row * 72 + q4] = av;
        }
#pragma unroll
        for (int it = 0; it < 8; it++) {
            int t = tid + 256 * it;
            int row = t >> 4, q4 = (t & 15) << 2;
            float4 bv = *(const float4*)(Bs + (size_t)(bn + row) * 2 * K + k0 * 2 + q4);
            *(float4*)&sm[9216 + row * 72 + q4] = bv;
        }
        __syncthreads();
#pragma unroll
        for (int ks = 0; ks < 4; ks++) {
            float ah[4][4], al[4][4], bh[4][2], bl[4][2];
#pragma unroll
            for (int mi = 0; mi < 4; mi++) {
                int base = (wm * 64 + mi * 16 + g) * 72 + (ks * 8 + tg) * 2;
                float2 p0 = *(float2*)&sm[base];
                float2 p1 = *(float2*)&sm[base + 8 * 72];
                float2 p2 = *(float2*)&sm[base + 8];
                float2 p3 = *(float2*)&sm[base + 8 * 72 + 8];
                ah[mi][0] = p0.x; al[mi][0] = p0.y;
                ah[mi][1] = p1.x; al[mi][1] = p1.y;
                ah[mi][2] = p2.x; al[mi][2] = p2.y;
                ah[mi][3] = p3.x; al[mi][3] = p3.y;
            }
#pragma unroll
            for (int ni = 0; ni < 4; ni++) {
                int base = 9216 + (wn * 32 + ni * 8 + g) * 72 + (ks * 8 + tg) * 2;
                float2 p0 = *(float2*)&sm[base];
                float2 p1 = *(float2*)&sm[base + 8];
                bh[ni][0] = p0.x; bl[ni][0] = p0.y;
                bh[ni][1] = p1.x; bl[ni][1] = p1.y;
            }
#pragma unroll
            for (int mi = 0; mi < 4; mi++)
#pragma unroll
                for (int ni = 0; ni < 4; ni++)
                    mma3(acc[mi][ni], ah[mi], al[mi], bh[ni], bl[ni]);
        }
        __syncthreads();
    }

#pragma unroll
    for (int mi = 0; mi < 4; mi++)
#pragma unroll
        for (int ni = 0; ni < 4; ni++) {
            int n0 = bn + wn * 32 + ni * 8 + tg * 2;
            float bb0 = bias[n0], bb1 = bias[n0 + 1];
#pragma unroll
            for (int rp = 0; rp < 2; rp++) {
                int m = bm + wm * 64 + mi * 16 + g + rp * 8;
                if (m >= M) continue;
                float v0 = acc[mi][ni][rp * 2]     + bb0;
                float v1 = acc[mi][ni][rp * 2 + 1] + bb1;
                if (mode == 0) {
                    *(float2*)(o0 + (size_t)m * N + n0) = make_float2(v0, v1);
                } else if (mode == 1) {
                    *(float4*)(o0 + (size_t)m * 2 * N + n0 * 2) = splitpk(v0, v1);
                } else {
                    if (n0 < E_) {
                        *(float4*)(o0 + (size_t)m * 2 * E_ + n0 * 2) =
                            splitpk(v0 + rwv[n0], v1 + rwv[n0 + 1]);
                        *(float4*)(o1 + (size_t)m * 2 * E_ + n0 * 2) =
                            splitpk(v0 + rrv[n0], v1 + rrv[n0 + 1]);
                    } else {
                        *(float4*)(o2 + (size_t)m * 4096 + (n0 - E_) * 2) =
                            splitpk(v0, v1);
                    }
                }
            }
        }
}

// ---------------- fused attention, i-tile 64, pre-split loads ------------------
// interleaved smem: (row,k) -> [row*40 + 2k]=hi, +1=lo  (stride 40: s2=20≡4 mod 16)
#define AQW  0
#define AQR  2560
#define AK   5120
#define AR   10240
#define AG   0
#define AP   0
#define AV   8448
#define ARMX 17920
#define ARSM 18176
#define ATTN_SMEM (18432 * 4)
#define SC_ 0.125f

__global__ __launch_bounds__(256) void attn_fused(const float* __restrict__ qws,
                                                  const float* __restrict__ qrs,
                                                  const float* __restrict__ kvs,
                                                  const float* __restrict__ rs,
                                                  float* __restrict__ atts)
{
    extern __shared__ float sm[];
    const int bh = blockIdx.y;
    const int b = bh / H_, h = bh % H_;
    const int i0 = blockIdx.x * 64;
    const int tid = threadIdx.x;
    const int w = tid >> 5, lane = tid & 31;
    const int g = lane >> 2, tg = lane & 3;
    const int wi = w >> 2, wj = w & 3;

    float m_run[2][2] = {{-1e30f, -1e30f}, {-1e30f, -1e30f}};
    float l_run[2][2] = {};
    float accO[2][2][4] = {};

    for (int j0 = 0; j0 < T_; j0 += 128) {
        const int pmin = j0 - i0 + (T_ - 64);
        float accA[2][4][4] = {};
        float accG[2][6][4] = {};

        for (int c = 0; c < 4; c++) {
            const int col2 = (h * D_ + c * 16) * 2;
            __syncthreads();
            // qw/qr: 64 rows x 8 float4 each (2 float4/thread each)
#pragma unroll
            for (int it = 0; it < 2; it++) {
                int t = tid + 256 * it;
                int row = t >> 3, q4 = (t & 7) << 2;
                size_t gofs = (size_t)((i0 + row) * B_ + b) * 2048 + col2 + q4;
                *(float4*)&sm[AQW + row * 40 + q4] = *(const float4*)(qws + gofs);
                *(float4*)&sm[AQR + row * 40 + q4] = *(const float4*)(qrs + gofs);
            }
            // k: 128 rows x 8 float4
#pragma unroll
            for (int it = 0; it < 4; it++) {
                int t = tid + 256 * it;
                int row = t >> 3, q4 = (t & 7) << 2;
                *(float4*)&sm[AK + row * 40 + q4] =
                    *(const float4*)(kvs + (size_t)((j0 + row) * B_ + b) * 4096 + col2 + q4);
            }
            // r window: 191 real + 1 zero row
#pragma unroll
            for (int it = 0; it < 6; it++) {
                int t = tid + 256 * it;
                int pl = t >> 3, q4 = (t & 7) << 2;
                float4 rv = (pl < 191)
                    ? *(const float4*)(rs + (size_t)((pmin + pl) * B_ + b) * 2048 + col2 + q4)
                    : make_float4(0.f, 0.f, 0.f, 0.f);
                *(float4*)&sm[AR + pl * 40 + q4] = rv;
            }
            __syncthreads();
#pragma unroll
            for (int ks = 0; ks < 2; ks++) {
                float aW[2][4], aWl[2][4], aR_[2][4], aRl[2][4];
#pragma unroll
                for (int mi = 0; mi < 2; mi++) {
                    int ra = (wi * 32 + mi * 16 + g) * 40 + (ks * 8 + tg) * 2;
                    float2 t0 = *(float2*)&sm[AQW + ra];
                    float2 t1 = *(float2*)&sm[AQW + ra + 8 * 40];
                    float2 t2 = *(float2*)&sm[AQW + ra + 8];
                    float2 t3 = *(float2*)&sm[AQW + ra + 8 * 40 + 8];
                    aW[mi][0] = t0.x; aWl[mi][0] = t0.y;
                    aW[mi][1] = t1.x; aWl[mi][1] = t1.y;
                    aW[mi][2] = t2.x; aWl[mi][2] = t2.y;
                    aW[mi][3] = t3.x; aWl[mi][3] = t3.y;
                    t0 = *(float2*)&sm[AQR + ra];
                    t1 = *(float2*)&sm[AQR + ra + 8 * 40];
                    t2 = *(float2*)&sm[AQR + ra + 8];
                    t3 = *(float2*)&sm[AQR + ra + 8 * 40 + 8];
                    aR_[mi][0] = t0.x; aRl[mi][0] = t0.y;
                    aR_[mi][1] = t1.x; aRl[mi][1] = t1.y;
                    aR_[mi][2] = t2.x; aRl[mi][2] = t2.y;
                    aR_[mi][3] = t3.x; aRl[mi][3] = t3.y;
                }
#pragma unroll
                for (int nj = 0; nj < 4; nj++) {
                    int rb = (wj * 32 + nj * 8 + g) * 40 + (ks * 8 + tg) * 2;
                    float2 b0 = *(float2*)&sm[AK + rb];
                    float2 b1 = *(float2*)&sm[AK + rb + 8];
                    float bhf[2] = {b0.x, b1.x}, blf[2] = {b0.y, b1.y};
                    mma3(accA[0][nj], aW[0], aWl[0], bhf, blf);
                    mma3(accA[1][nj], aW[1], aWl[1], bhf, blf);
                }
#pragma unroll
                for (int ng = 0; ng < 6; ng++) {
                    int rb = (wj * 48 + ng * 8 + g) * 40 + (ks * 8 + tg) * 2;
                    float2 b0 = *(float2*)&sm[AR + rb];
                    float2 b1 = *(float2*)&sm[AR + rb + 8];
                    float bhf[2] = {b0.x, b1.x}, blf[2] = {b0.y, b1.y};
                    mma3(accG[0][ng], aR_[0], aRl[0], bhf, blf);
                    mma3(accG[1][ng], aR_[1], aRl[1], bhf, blf);
                }
            }
        }
        __syncthreads();

        // stage G[64][196]
#pragma unroll
        for (int mi = 0; mi < 2; mi++)
#pragma unroll
            for (int ng = 0; ng < 6; ng++) {
                int row = wi * 32 + mi * 16 + g;
                int cc = wj * 48 + ng * 8 + tg * 2;
                sm[AG + row * 196 + cc]           = accG[mi][ng][0];
                sm[AG + row * 196 + cc + 1]       = accG[mi][ng][1];
                sm[AG + (row + 8) * 196 + cc]     = accG[mi][ng][2];
                sm[AG + (row + 8) * 196 + cc + 1] = accG[mi][ng][3];
            }
        __syncthreads();

        float tmax[2][2] = {{-1e30f, -1e30f}, {-1e30f, -1e30f}};
#pragma unroll
        for (int mi = 0; mi < 2; mi++)
#pragma unroll
            for (int nj = 0; nj < 4; nj++) {
                int il = wi * 32 + mi * 16 + g;
                int jl = wj * 32 + nj * 8 + tg * 2;
                int il2 = il + 8;
                accA[mi][nj][0] += sm[AG + il * 196 + (jl - il + 63)];
                accA[mi][nj][1] += sm[AG + il * 196 + (jl + 1 - il + 63)];
                accA[mi][nj][2] += sm[AG + il2 * 196 + (jl - il2 + 63)];
                accA[mi][nj][3] += sm[AG + il2 * 196 + (jl + 1 - il2 + 63)];
                tmax[mi][0] = fmaxf(tmax[mi][0], fmaxf(accA[mi][nj][0], accA[mi][nj][1]));
                tmax[mi][1] = fmaxf(tmax[mi][1], fmaxf(accA[mi][nj][2], accA[mi][nj][3]));
            }
#pragma unroll
        for (int mi = 0; mi < 2; mi++)
#pragma unroll
            for (int rp = 0; rp < 2; rp++) {
                float v = tmax[mi][rp];
                v = fmaxf(v, __shfl_xor_sync(0xffffffffu, v, 1));
                v = fmaxf(v, __shfl_xor_sync(0xffffffffu, v, 2));
                tmax[mi][rp] = v;
            }
        if (tg == 0) {
#pragma unroll
            for (int mi = 0; mi < 2; mi++)
#pragma unroll
                for (int rp = 0; rp < 2; rp++) {
                    int row = wi * 32 + mi * 16 + g + rp * 8;
                    sm[ARMX + row * 4 + wj] = tmax[mi][rp];
                }
        }
        __syncthreads();

        float mnew[2][2], fsc[2][2];
#pragma unroll
        for (int mi = 0; mi < 2; mi++)
#pragma unroll
            for (int rp = 0; rp < 2; rp++) {
                int row = wi * 32 + mi * 16 + g + rp * 8;
                float mt = fmaxf(fmaxf(sm[ARMX + row * 4 + 0], sm[ARMX + row * 4 + 1]),
                                 fmaxf(sm[ARMX + row * 4 + 2], sm[ARMX + row * 4 + 3]));
                mnew[mi][rp] = fmaxf(m_run[mi][rp], mt);
                fsc[mi][rp] = __expf((m_run[mi][rp] - mnew[mi][rp]) * SC_);
            }

        float tsum[2][2] = {};
#pragma unroll
        for (int mi = 0; mi < 2; mi++)
#pragma unroll
            for (int nj = 0; nj < 4; nj++) {
                int il = wi * 32 + mi * 16 + g;
                int jl = wj * 32 + nj * 8 + tg * 2;
                float p0 = __expf((accA[mi][nj][0] - mnew[mi][0]) * SC_);
                float p1 = __expf((accA[mi][nj][1] - mnew[mi][0]) * SC_);
                float p2 = __expf((accA[mi][nj][2] - mnew[mi][1]) * SC_);
                float p3 = __expf((accA[mi][nj][3] - mnew[mi][1]) * SC_);
                tsum[mi][0] += p0 + p1;
                tsum[mi][1] += p2 + p3;
                sm[AP + il * 132 + jl]           = __uint_as_float(f2tf(p0));
                sm[AP + il * 132 + jl + 1]       = __uint_as_float(f2tf(p1));
                sm[AP + (il + 8) * 132 + jl]     = __uint_as_float(f2tf(p2));
                sm[AP + (il + 8) * 132 + jl + 1] = __uint_as_float(f2tf(p3));
            }
#pragma unroll
        for (int mi = 0; mi < 2; mi++)
#pragma unroll
            for (int rp = 0; rp < 2; rp++) {
                float v = tsum[mi][rp];
                v += __shfl_xor_sync(0xffffffffu, v, 1);
                v += __shfl_xor_sync(0xffffffffu, v, 2);
                tsum[mi][rp] = v;
            }
        if (tg == 0) {
#pragma unroll
            for (int mi = 0; mi < 2; mi++)
#pragma unroll
                for (int rp = 0; rp < 2; rp++) {
                    int row = wi * 32 + mi * 16 + g + rp * 8;
                    sm[ARSM + row * 4 + wj] = tsum[mi][rp];
                }
        }
        __syncthreads();

#pragma unroll
        for (int mi = 0; mi < 2; mi++)
#pragma unroll
            for (int rp = 0; rp < 2; rp++) {
                int row = wi * 32 + mi * 16 + g + rp * 8;
                float lt = sm[ARSM + row * 4 + 0] + sm[ARSM + row * 4 + 1]
                         + sm[ARSM + row * 4 + 2] + sm[ARSM + row * 4 + 3];
                l_run[mi][rp] = l_run[mi][rp] * fsc[mi][rp] + lt;
                m_run[mi][rp] = mnew[mi][rp];
            }
#pragma unroll
        for (int mi = 0; mi < 2; mi++)
#pragma unroll
            for (int nd = 0; nd < 2; nd++) {
                accO[mi][nd][0] *= fsc[mi][0];
                accO[mi][nd][1] *= fsc[mi][0];
                accO[mi][nd][2] *= fsc[mi][1];
                accO[mi][nd][3] *= fsc[mi][1];
            }

        // PV: V stride 144 (s2=72≡8 mod 16)
        for (int jc = 0; jc < 2; jc++) {
            __syncthreads();
#pragma unroll
            for (int it = 0; it < 8; it++) {
                int t = tid + 256 * it;
                int row = t >> 5, q4 = (t & 31) << 2;
                *(float4*)&sm[AV + row * 144 + q4] =
                    *(const float4*)(kvs + (size_t)((j0 + jc * 64 + row) * B_ + b) * 4096
                                     + 2048 + h * 128 + q4);
            }
            __syncthreads();
#pragma unroll
            for (int ks = 0; ks < 8; ks++) {
                float a[2][4];
#pragma unroll
                for (int mi = 0; mi < 2; mi++) {
                    int ra = (wi * 32 + mi * 16 + g) * 132 + jc * 64 + ks * 8 + tg;
                    a[mi][0] = sm[AP + ra];
                    a[mi][1] = sm[AP + ra + 8 * 132];
                    a[mi][2] = sm[AP + ra + 4];
                    a[mi][3] = sm[AP + ra + 8 * 132 + 4];
                }
#pragma unroll
                for (int nd = 0; nd < 2; nd++) {
                    int col = wj * 16 + nd * 8 + g;
                    float2 v0 = *(float2*)&sm[AV + (ks * 8 + tg) * 144 + col * 2];
                    float2 v1 = *(float2*)&sm[AV + (ks * 8 + tg + 4) * 144 + col * 2];
                    float vh[2] = {v0.x, v1.x}, vl[2] = {v0.y, v1.y};
#pragma unroll
                    for (int mi = 0; mi < 2; mi++) {
                        mma8(accO[mi][nd], a[mi], vh);
                        mma8(accO[mi][nd], a[mi], vl);
                    }
                }
            }
        }
    }

    // epilogue: normalize, split, store interleaved for out-proj
    float inv[2][2];
#pragma unroll
    for (int mi = 0; mi < 2; mi++)
#pragma unroll
        for (int rp = 0; rp < 2; rp++)
            inv[mi][rp] = 1.0f / l_run[mi][rp];
#pragma unroll
    for (int mi = 0; mi < 2; mi++)
#pragma unroll
        for (int nd = 0; nd < 2; nd++) {
            int row = wi * 32 + mi * 16 + g;
            int col2 = (h * D_ + wj * 16 + nd * 8 + tg * 2) * 2;
            *(float4*)(atts + (size_t)((i0 + row) * B_ + b) * 2048 + col2) =
                splitpk(accO[mi][nd][0] * inv[mi][0], accO[mi][nd][1] * inv[mi][0]);
            *(float4*)(atts + (size_t)((i0 + row + 8) * B_ + b) * 2048 + col2) =
                splitpk(accO[mi][nd][2] * inv[mi][1], accO[mi][nd][3] * inv[mi][1]);
        }
}

// ---------------- launch ----------------
extern "C" void kernel_launch(void* const* d_in, const int* in_sizes, int n_in,
                              void* d_out, int out_size)
{
    (void)in_sizes; (void)n_in; (void)out_size;
    const float* input  = (const float*)d_in[0];
    const float* pos    = (const float*)d_in[1];
    const float* factor = (const float*)d_in[2];
    const float* w_in   = (const float*)d_in[3];
    const float* w_pos  = (const float*)d_in[4];
    const float* w_out  = (const float*)d_in[5];
    const float* bw_in  = (const float*)d_in[6];
    const float* bw_pos = (const float*)d_in[7];
    const float* bw_out = (const float*)d_in[8];
    const float* rwb    = (const float*)d_in[9];
    const float* rrb    = (const float*)d_in[10];

    float *pWins, *pWposs, *pWouts, *pbin, *pbpos, *pbout, *prw, *prr;
    float *pins, *pposs, *pqws, *pqrs, *pkvs, *prs, *patts;
    cudaGetSymbolAddress((void**)&pWins,  g_Wins);
    cudaGetSymbolAddress((void**)&pWposs, g_Wposs);
    cudaGetSymbolAddress((void**)&pWouts, g_Wouts);
    cudaGetSymbolAddress((void**)&pbin,   g_bin);
    cudaGetSymbolAddress((void**)&pbpos,  g_bpos);
    cudaGetSymbolAddress((void**)&pbout,  g_bout);
    cudaGetSymbolAddress((void**)&prw,    g_rw);
    cudaGetSymbolAddress((void**)&prr,    g_rr);
    cudaGetSymbolAddress((void**)&pins,   g_ins);
    cudaGetSymbolAddress((void**)&pposs,  g_poss);
    cudaGetSymbolAddress((void**)&pqws,   g_qws);
    cudaGetSymbolAddress((void**)&pqrs,   g_qrs);
    cudaGetSymbolAddress((void**)&pkvs,   g_kvs);
    cudaGetSymbolAddress((void**)&prs,    g_rs);
    cudaGetSymbolAddress((void**)&patts,  g_atts);

    cudaFuncSetAttribute(attn_fused, cudaFuncAttributeMaxDynamicSharedMemorySize, ATTN_SMEM);

    // 1) hypernet (weights split)
    hyper_all<<<(HN7 + 255) / 256, 256>>>(w_in, w_pos, w_out, bw_in, bw_pos, bw_out,
                                          rwb, rrb, factor,
                                          pWins, pWposs, pWouts, pbin, pbpos, pbout, prw, prr);

    // 2) split input & pos
    split_inputs<<<(NIN4 + NPOS4 + 255) / 256, 256>>>(input, pos, pins, pposs);

    // 3) qkv projection: q->qws/qrs (rw/rr pre-added, split), kv->kvs (split)
    gemm3s<<<dim3(3 * E_ / 128, TB_ / 128), 256>>>(pins, pWins, pbin,
                                                   pqws, pqrs, pkvs, prw, prr,
                                                   TB_, 3 * E_, E_, 2);
    // 4) pos projection -> rs (split)
    gemm3s<<<dim3(E_ / 128, (RB_ + 127) / 128), 256>>>(pposs, pWposs, pbpos,
                                                       prs, 0, 0, 0, 0,
                                                       RB_, E_, E_, 1);

    // 5) fused attention (i-tile 64, all loads pre-split)
    attn_fused<<<dim3(T_ / 64, B_ * H_), 256, ATTN_SMEM>>>(pqws, pqrs, pkvs, prs, patts);

    // 6) output projection -> d_out (fp32)
    gemm3s<<<dim3(E_ / 128, TB_ / 128), 256>>>(patts, pWouts, pbout,
                                               (float*)d_out, 0, 0, 0, 0,
                                               TB_, E_, E_, 0);
}

// round 10
// speedup vs baseline: 1.4797x; 1.4797x over previous
#include <cuda_runtime.h>
#include <math.h>

#define T_  1024
#define B_  2
#define E_  1024
#define H_  16
#define D_  64
#define TB_ 2048
#define RB_ 4094

// ---------------- scratch ----------------
__device__ float g_Win [3 * E_ * E_];
__device__ float g_Wpos[E_ * E_];
__device__ float g_Wout[E_ * E_];
__device__ float g_bin [3 * E_];
__device__ float g_bpos[E_];
__device__ float g_bout[E_];
__device__ float g_rw  [E_];
__device__ float g_rr  [E_];
__device__ float g_qkv [TB_ * 3 * E_];
__device__ float g_r   [RB_ * E_];
__device__ float g_att [TB_ * E_];

// ---------------- tf32 helpers ----------------
__device__ __forceinline__ unsigned f2tf(float f) {
    unsigned r; asm("cvt.rna.tf32.f32 %0, %1;" : "=r"(r) : "f"(f)); return r;
}
__device__ __forceinline__ void split2(float v, float& hi, float& lo) {
    hi = __uint_as_float(f2tf(v));
    lo = __uint_as_float(f2tf(v - hi));
}
__device__ __forceinline__ void mma8(float* c, const float* a, const float* b) {
    asm volatile("mma.sync.aligned.m16n8k8.row.col.f32.tf32.tf32.f32 "
                 "{%0,%1,%2,%3},{%4,%5,%6,%7},{%8,%9},{%0,%1,%2,%3};"
                 : "+f"(c[0]), "+f"(c[1]), "+f"(c[2]), "+f"(c[3])
                 : "r"(__float_as_uint(a[0])), "r"(__float_as_uint(a[1])),
                   "r"(__float_as_uint(a[2])), "r"(__float_as_uint(a[3])),
                   "r"(__float_as_uint(b[0])), "r"(__float_as_uint(b[1])));
}
__device__ __forceinline__ void mma3(float* c, const float* ah, const float* al,
                                     const float* bh, const float* bl) {
    mma8(c, ah, bh);
    mma8(c, ah, bl);
    mma8(c, al, bh);
}

// ---------------- fused hypernet ----------------
#define HN0 3145728
#define HN1 (HN0 + 1048576)
#define HN2 (HN1 + 1048576)
#define HN3 (HN2 + 3072)
#define HN4 (HN3 + 1024)
#define HN5 (HN4 + 1024)
#define HN6 (HN5 + 1024)
#define HN7 (HN6 + 1024)

__global__ __launch_bounds__(256) void hyper_all(
    const float* __restrict__ w_in,  const float* __restrict__ w_pos,
    const float* __restrict__ w_out, const float* __restrict__ b_in,
    const float* __restrict__ b_pos, const float* __restrict__ b_out,
    const float* __restrict__ rwb,   const float* __restrict__ rrb,
    const float* __restrict__ f,
    float* __restrict__ oWin,  float* __restrict__ oWpos,
    float* __restrict__ oWout, float* __restrict__ obin,
    float* __restrict__ obpos, float* __restrict__ obout,
    float* __restrict__ orw,   float* __restrict__ orr)
{
    int idx = blockIdx.x * blockDim.x + threadIdx.x;
    if (idx >= HN7) return;
    const float* src; float* dst; int off;
    if      (idx < HN0) { src = w_in;  dst = oWin;  off = idx; }
    else if (idx < HN1) { src = w_pos; dst = oWpos; off = idx - HN0; }
    else if (idx < HN2) { src = w_out; dst = oWout; off = idx - HN1; }
    else if (idx < HN3) { src = b_in;  dst = obin;  off = idx - HN2; }
    else if (idx < HN4) { src = b_pos; dst = obpos; off = idx - HN3; }
    else if (idx < HN5) { src = b_out; dst = obout; off = idx - HN4; }
    else if (idx < HN6) { src = rwb;   dst = orw;   off = idx - HN5; }
    else                { src = rrb;   dst = orr;   off = idx - HN6; }
    const float4* wp = (const float4*)(src + (size_t)off * 8);
    float4 a = wp[0], b = wp[1];
    float4 f0 = *(const float4*)f;
    float4 f1 = *(const float4*)(f + 4);
    dst[off] = a.x*f0.x + a.y*f0.y + a.z*f0.z + a.w*f0.w
             + b.x*f1.x + b.y*f1.y + b.z*f1.z + b.w*f1.w;
}

// ---------------- 3xtf32 NT GEMM with register double-buffer -------------------
#define GA_H 0
#define GA_L 4608
#define GB_H 9216
#define GB_L 13824
#define GEMM_SMEM (18432 * 4)

__global__ __launch_bounds__(256) void gemm3(const float* __restrict__ A,
                                             const float* __restrict__ Bm,
                                             const float* __restrict__ bias,
                                             float* __restrict__ C,
                                             int M, int N, int K)
{
    extern __shared__ float sm[];
    int bm = blockIdx.y * 128, bn = blockIdx.x * 128;
    int tid = threadIdx.x;
    int w = tid >> 5, lane = tid & 31;
    int g = lane >> 2, tg = lane & 3;
    int wm = w & 1, wn = w >> 1;
    float acc[4][4][4] = {};

    float4 pa[4], pb[4];
    // prefetch k0 = 0
#pragma unroll
    for (int it = 0; it < 4; it++) {
        int t = tid + 256 * it;
        int row = t >> 3, kq = (t & 7) << 2;
        int m = bm + row;
        pa[it] = (m < M) ? *(const float4*)(A + (size_t)m * K + kq)
                         : make_float4(0.f, 0.f, 0.f, 0.f);
        pb[it] = *(const float4*)(Bm + (size_t)(bn + row) * K + kq);
    }

    for (int k0 = 0; k0 < K; k0 += 32) {
        // store prefetched tile (split) to smem
#pragma unroll
        for (int it = 0; it < 4; it++) {
            int t = tid + 256 * it;
            int row = t >> 3, kq = (t & 7) << 2;
            float4 ah, al;
            split2(pa[it].x, ah.x, al.x); split2(pa[it].y, ah.y, al.y);
            split2(pa[it].z, ah.z, al.z); split2(pa[it].w, ah.w, al.w);
            *(float4*)&sm[GA_H + row * 36 + kq] = ah;
            *(float4*)&sm[GA_L + row * 36 + kq] = al;
            float4 bh, bl;
            split2(pb[it].x, bh.x, bl.x); split2(pb[it].y, bh.y, bl.y);
            split2(pb[it].z, bh.z, bl.z); split2(pb[it].w, bh.w, bl.w);
            *(float4*)&sm[GB_H + row * 36 + kq] = bh;
            *(float4*)&sm[GB_L + row * 36 + kq] = bl;
        }
        __syncthreads();

        // prefetch next k-tile while computing this one
        if (k0 + 32 < K) {
#pragma unroll
            for (int it = 0; it < 4; it++) {
                int t = tid + 256 * it;
                int row = t >> 3, kq = (t & 7) << 2;
                int m = bm + row;
                pa[it] = (m < M) ? *(const float4*)(A + (size_t)m * K + k0 + 32 + kq)
                                 : make_float4(0.f, 0.f, 0.f, 0.f);
                pb[it] = *(const float4*)(Bm + (size_t)(bn + row) * K + k0 + 32 + kq);
            }
        }

#pragma unroll
        for (int ks = 0; ks < 4; ks++) {
            float ah[4][4], al[4][4], bh[4][2], bl[4][2];
#pragma unroll
            for (int mi = 0; mi < 4; mi++) {
                int r0 = (wm * 64 + mi * 16 + g) * 36 + ks * 8 + tg;
                ah[mi][0] = sm[GA_H + r0];
                ah[mi][1] = sm[GA_H + r0 + 8 * 36];
                ah[mi][2] = sm[GA_H + r0 + 4];
                ah[mi][3] = sm[GA_H + r0 + 8 * 36 + 4];
                al[mi][0] = sm[GA_L + r0];
                al[mi][1] = sm[GA_L + r0 + 8 * 36];
                al[mi][2] = sm[GA_L + r0 + 4];
                al[mi][3] = sm[GA_L + r0 + 8 * 36 + 4];
            }
#pragma unroll
            for (int ni = 0; ni < 4; ni++) {
                int r0 = (wn * 32 + ni * 8 + g) * 36 + ks * 8 + tg;
                bh[ni][0] = sm[GB_H + r0];
                bh[ni][1] = sm[GB_H + r0 + 4];
                bl[ni][0] = sm[GB_L + r0];
                bl[ni][1] = sm[GB_L + r0 + 4];
            }
#pragma unroll
            for (int mi = 0; mi < 4; mi++)
#pragma unroll
                for (int ni = 0; ni < 4; ni++)
                    mma3(acc[mi][ni], ah[mi], al[mi], bh[ni], bl[ni]);
        }
        __syncthreads();
    }

#pragma unroll
    for (int mi = 0; mi < 4; mi++)
#pragma unroll
        for (int ni = 0; ni < 4; ni++) {
            int m0 = bm + wm * 64 + mi * 16 + g;
            int n0 = bn + wn * 32 + ni * 8 + tg * 2;
            float bb0 = bias[n0], bb1 = bias[n0 + 1];
            if (m0 < M) {
                float2 o = {acc[mi][ni][0] + bb0, acc[mi][ni][1] + bb1};
                *(float2*)(C + (size_t)m0 * N + n0) = o;
            }
            if (m0 + 8 < M) {
                float2 o = {acc[mi][ni][2] + bb0, acc[mi][ni][3] + bb1};
                *(float2*)(C + (size_t)(m0 + 8) * N + n0) = o;
            }
        }
}

// ---------------- fused attention (identical to R5 best) -----------------------
#define AQWH 0
#define AQWL 1280
#define AQRH 2560
#define AQRL 3840
#define AKH  5120
#define AKL  7680
#define ARH  10240
#define ARL  14080
#define AG   0
#define AP   0
#define AVH  8448
#define AVL  13056
#define ARMX 17920
#define ARSM 18176
#define ATTN_SMEM (18432 * 4)
#define SC_ 0.125f

__global__ __launch_bounds__(256) void attn_fused(const float* __restrict__ qkv,
                                                  const float* __restrict__ rproj,
                                                  const float* __restrict__ rw,
                                                  const float* __restrict__ rr,
                                                  float* __restrict__ att)
{
    extern __shared__ float sm[];
    const int bh = blockIdx.y;
    const int b = bh / H_, h = bh % H_;
    const int i0 = blockIdx.x * 64;
    const int tid = threadIdx.x;
    const int w = tid >> 5, lane = tid & 31;
    const int g = lane >> 2, tg = lane & 3;
    const int wi = w >> 2, wj = w & 3;

    float m_run[2][2] = {{-1e30f, -1e30f}, {-1e30f, -1e30f}};
    float l_run[2][2] = {};
    float accO[2][2][4] = {};

    for (int j0 = 0; j0 < T_; j0 += 128) {
        const int pmin = j0 - i0 + (T_ - 64);
        float accA[2][4][4] = {};
        float accG[2][6][4] = {};

        for (int c = 0; c < 4; c++) {
            const int col0 = h * D_ + c * 16;
            __syncthreads();
            {
                int il = tid >> 2, kq = (tid & 3) << 2;
                float4 qv = *(const float4*)(qkv + (size_t)((i0 + il) * B_ + b) * (3 * E_) + col0 + kq);
                float4 rwv = *(const float4*)(rw + col0 + kq);
                float4 rrv = *(const float4*)(rr + col0 + kq);
                float4 hw, lw, hr, lr;
                split2(qv.x + rwv.x, hw.x, lw.x); split2(qv.y + rwv.y, hw.y, lw.y);
                split2(qv.z + rwv.z, hw.z, lw.z); split2(qv.w + rwv.w, hw.w, lw.w);
                split2(qv.x + rrv.x, hr.x, lr.x); split2(qv.y + rrv.y, hr.y, lr.y);
                split2(qv.z + rrv.z, hr.z, lr.z); split2(qv.w + rrv.w, hr.w, lr.w);
                *(float4*)&sm[AQWH + il * 20 + kq] = hw;
                *(float4*)&sm[AQWL + il * 20 + kq] = lw;
                *(float4*)&sm[AQRH + il * 20 + kq] = hr;
                *(float4*)&sm[AQRL + il * 20 + kq] = lr;
            }
#pragma unroll
            for (int it = 0; it < 2; it++) {
                int t = tid + 256 * it;
                int il = t >> 2, kq = (t & 3) << 2;
                float4 kv = *(const float4*)(qkv + (size_t)((j0 + il) * B_ + b) * (3 * E_) + E_ + col0 + kq);
                float4 hk, lk;
                split2(kv.x, hk.x, lk.x); split2(kv.y, hk.y, lk.y);
                split2(kv.z, hk.z, lk.z); split2(kv.w, hk.w, lk.w);
                *(float4*)&sm[AKH + il * 20 + kq] = hk;
                *(float4*)&sm[AKL + il * 20 + kq] = lk;
            }
#pragma unroll
            for (int it = 0; it < 3; it++) {
                int t = tid + 256 * it;
                int pl = t >> 2, kq = (t & 3) << 2;
                float4 rv = (pl < 191)
                    ? *(const float4*)(rproj + (size_t)((pmin + pl) * B_ + b) * E_ + col0 + kq)
                    : make_float4(0.f, 0.f, 0.f, 0.f);
                float4 hh, ll;
                split2(rv.x, hh.x, ll.x); split2(rv.y, hh.y, ll.y);
                split2(rv.z, hh.z, ll.z); split2(rv.w, hh.w, ll.w);
                *(float4*)&sm[ARH + pl * 20 + kq] = hh;
                *(float4*)&sm[ARL + pl * 20 + kq] = ll;
            }
            __syncthreads();
#pragma unroll
            for (int ks = 0; ks < 2; ks++) {
                float aWh[2][4], aWl[2][4], aRh[2][4], aRl[2][4];
#pragma unroll
                for (int mi = 0; mi < 2; mi++) {
                    int r0 = (wi * 32 + mi * 16 + g) * 20 + ks * 8 + tg;
                    aWh[mi][0] = sm[AQWH + r0];
                    aWh[mi][1] = sm[AQWH + r0 + 8 * 20];
                    aWh[mi][2] = sm[AQWH + r0 + 4];
                    aWh[mi][3] = sm[AQWH + r0 + 8 * 20 + 4];
                    aWl[mi][0] = sm[AQWL + r0];
                    aWl[mi][1] = sm[AQWL + r0 + 8 * 20];
                    aWl[mi][2] = sm[AQWL + r0 + 4];
                    aWl[mi][3] = sm[AQWL + r0 + 8 * 20 + 4];
                    aRh[mi][0] = sm[AQRH + r0];
                    aRh[mi][1] = sm[AQRH + r0 + 8 * 20];
                    aRh[mi][2] = sm[AQRH + r0 + 4];
                    aRh[mi][3] = sm[AQRH + r0 + 8 * 20 + 4];
                    aRl[mi][0] = sm[AQRL + r0];
                    aRl[mi][1] = sm[AQRL + r0 + 8 * 20];
                    aRl[mi][2] = sm[AQRL + r0 + 4];
                    aRl[mi][3] = sm[AQRL + r0 + 8 * 20 + 4];
                }
#pragma unroll
                for (int nj = 0; nj < 4; nj++) {
                    float bhf[2], blf[2];
                    int r0 = (wj * 32 + nj * 8 + g) * 20 + ks * 8 + tg;
                    bhf[0] = sm[AKH + r0]; bhf[1] = sm[AKH + r0 + 4];
                    blf[0] = sm[AKL + r0]; blf[1] = sm[AKL + r0 + 4];
                    mma3(accA[0][nj], aWh[0], aWl[0], bhf, blf);
                    mma3(accA[1][nj], aWh[1], aWl[1], bhf, blf);
                }
#pragma unroll
                for (int ng = 0; ng < 6; ng++) {
                    float bhf[2], blf[2];
                    int r0 = (wj * 48 + ng * 8 + g) * 20 + ks * 8 + tg;
                    bhf[0] = sm[ARH + r0]; bhf[1] = sm[ARH + r0 + 4];
                    blf[0] = sm[ARL + r0]; blf[1] = sm[ARL + r0 + 4];
                    mma3(accG[0][ng], aRh[0], aRl[0], bhf, blf);
                    mma3(accG[1][ng], aRh[1], aRl[1], bhf, blf);
                }
            }
        }
        __syncthreads();

#pragma unroll
        for (int mi = 0; mi < 2; mi++)
#pragma unroll
            for (int ng = 0; ng < 6; ng++) {
                int row = wi * 32 + mi * 16 + g;
                int cc = wj * 48 + ng * 8 + tg * 2;
                sm[AG + row * 196 + cc]           = accG[mi][ng][0];
                sm[AG + row * 196 + cc + 1]       = accG[mi][ng][1];
                sm[AG + (row + 8) * 196 + cc]     = accG[mi][ng][2];
                sm[AG + (row + 8) * 196 + cc + 1] = accG[mi][ng][3];
            }
        __syncthreads();

        float tmax[2][2] = {{-1e30f, -1e30f}, {-1e30f, -1e30f}};
#pragma unroll
        for (int mi = 0; mi < 2; mi++)
#pragma unroll
            for (int nj = 0; nj < 4; nj++) {
                int il = wi * 32 + mi * 16 + g;
                int jl = wj * 32 + nj * 8 + tg * 2;
                int il2 = il + 8;
                accA[mi][nj][0] += sm[AG + il * 196 + (jl - il + 63)];
                accA[mi][nj][1] += sm[AG + il * 196 + (jl + 1 - il + 63)];
                accA[mi][nj][2] += sm[AG + il2 * 196 + (jl - il2 + 63)];
                accA[mi][nj][3] += sm[AG + il2 * 196 + (jl + 1 - il2 + 63)];
                tmax[mi][0] = fmaxf(tmax[mi][0], fmaxf(accA[mi][nj][0], accA[mi][nj][1]));
                tmax[mi][1] = fmaxf(tmax[mi][1], fmaxf(accA[mi][nj][2], accA[mi][nj][3]));
            }
#pragma unroll
        for (int mi = 0; mi < 2; mi++)
#pragma unroll
            for (int rp = 0; rp < 2; rp++) {
                float v = tmax[mi][rp];
                v = fmaxf(v, __shfl_xor_sync(0xffffffffu, v, 1));
                v = fmaxf(v, __shfl_xor_sync(0xffffffffu, v, 2));
                tmax[mi][rp] = v;
            }
        if (tg == 0) {
#pragma unroll
            for (int mi = 0; mi < 2; mi++)
#pragma unroll
                for (int rp = 0; rp < 2; rp++) {
                    int row = wi * 32 + mi * 16 + g + rp * 8;
                    sm[ARMX + row * 4 + wj] = tmax[mi][rp];
                }
        }
        __syncthreads();

        float mnew[2][2], fsc[2][2];
#pragma unroll
        for (int mi = 0; mi < 2; mi++)
#pragma unroll
            for (int rp = 0; rp < 2; rp++) {
                int row = wi * 32 + mi * 16 + g + rp * 8;
                float mt = fmaxf(fmaxf(sm[ARMX + row * 4 + 0], sm[ARMX + row * 4 + 1]),
                                 fmaxf(sm[ARMX + row * 4 + 2], sm[ARMX + row * 4 + 3]));
                mnew[mi][rp] = fmaxf(m_run[mi][rp], mt);
                fsc[mi][rp] = __expf((m_run[mi][rp] - mnew[mi][rp]) * SC_);
            }

        float tsum[2][2] = {};
#pragma unroll
        for (int mi = 0; mi < 2; mi++)
#pragma unroll
            for (int nj = 0; nj < 4; nj++) {
                int il = wi * 32 + mi * 16 + g;
                int jl = wj * 32 + nj * 8 + tg * 2;
                float p0 = __expf((accA[mi][nj][0] - mnew[mi][0]) * SC_);
                float p1 = __expf((accA[mi][nj][1] - mnew[mi][0]) * SC_);
                float p2 = __expf((accA[mi][nj][2] - mnew[mi][1]) * SC_);
                float p3 = __expf((accA[mi][nj][3] - mnew[mi][1]) * SC_);
                tsum[mi][0] += p0 + p1;
                tsum[mi][1] += p2 + p3;
                sm[AP + il * 132 + jl]           = __uint_as_float(f2tf(p0));
                sm[AP + il * 132 + jl + 1]       = __uint_as_float(f2tf(p1));
                sm[AP + (il + 8) * 132 + jl]     = __uint_as_float(f2tf(p2));
                sm[AP + (il + 8) * 132 + jl + 1] = __uint_as_float(f2tf(p3));
            }
#pragma unroll
        for (int mi = 0; mi < 2; mi++)
#pragma unroll
            for (int rp = 0; rp < 2; rp++) {
                float v = tsum[mi][rp];
                v += __shfl_xor_sync(0xffffffffu, v, 1);
                v += __shfl_xor_sync(0xffffffffu, v, 2);
                tsum[mi][rp] = v;
            }
        if (tg == 0) {
#pragma unroll
            for (int mi = 0; mi < 2; mi++)
#pragma unroll
                for (int rp = 0; rp < 2; rp++) {
                    int row = wi * 32 + mi * 16 + g + rp * 8;
                    sm[ARSM + row * 4 + wj] = tsum[mi][rp];
                }
        }
        __syncthreads();

#pragma unroll
        for (int mi = 0; mi < 2; mi++)
#pragma unroll
            for (int rp = 0; rp < 2; rp++) {
                int row = wi * 32 + mi * 16 + g + rp * 8;
                float lt = sm[ARSM + row * 4 + 0] + sm[ARSM + row * 4 + 1]
                         + sm[ARSM + row * 4 + 2] + sm[ARSM + row * 4 + 3];
                l_run[mi][rp] = l_run[mi][rp] * fsc[mi][rp] + lt;
                m_run[mi][rp] = mnew[mi][rp];
            }
#pragma unroll
        for (int mi = 0; mi < 2; mi++)
#pragma unroll
            for (int nd = 0; nd < 2; nd++) {
                accO[mi][nd][0] *= fsc[mi][0];
                accO[mi][nd][1] *= fsc[mi][0];
                accO[mi][nd][2] *= fsc[mi][1];
                accO[mi][nd][3] *= fsc[mi][1];
            }

        for (int jc = 0; jc < 2; jc++) {
            __syncthreads();
#pragma unroll
            for (int it = 0; it < 4; it++) {
                int t = tid + 256 * it;
                int row = t >> 4, dq = (t & 15) << 2;
                float4 vv = *(const float4*)(qkv + (size_t)((j0 + jc * 64 + row) * B_ + b) * (3 * E_)
                                             + 2 * E_ + h * D_ + dq);
                float4 hh, ll;
                split2(vv.x, hh.x, ll.x); split2(vv.y, hh.y, ll.y);
                split2(vv.z, hh.z, ll.z); split2(vv.w, hh.w, ll.w);
                *(float4*)&sm[AVH + row * 72 + dq] = hh;
                *(float4*)&sm[AVL + row * 72 + dq] = ll;
            }
            __syncthreads();
#pragma unroll
            for (int ks = 0; ks < 8; ks++) {
                float a[2][4];
#pragma unroll
                for (int mi = 0; mi < 2; mi++) {
                    int r0 = (wi * 32 + mi * 16 + g) * 132 + jc * 64 + ks * 8 + tg;
                    a[mi][0] = sm[AP + r0];
                    a[mi][1] = sm[AP + r0 + 8 * 132];
                    a[mi][2] = sm[AP + r0 + 4];
                    a[mi][3] = sm[AP + r0 + 8 * 132 + 4];
                }
#pragma unroll
                for (int nd = 0; nd < 2; nd++) {
                    int col = wj * 16 + nd * 8 + g;
                    float bhf[2], blf[2];
                    bhf[0] = sm[AVH + (ks * 8 + tg) * 72 + col];
                    bhf[1] = sm[AVH + (ks * 8 + tg + 4) * 72 + col];
                    blf[0] = sm[AVL + (ks * 8 + tg) * 72 + col];
                    blf[1] = sm[AVL + (ks * 8 + tg + 4) * 72 + col];
#pragma unroll
                    for (int mi = 0; mi < 2; mi++) {
                        mma8(accO[mi][nd], a[mi], bhf);
                        mma8(accO[mi][nd], a[mi], blf);
                    }
                }
            }
        }
    }

    float inv[2][2];
#pragma unroll
    for (int mi = 0; mi < 2; mi++)
#pragma unroll
        for (int rp = 0; rp < 2; rp++)
            inv[mi][rp] = 1.0f / l_run[mi][rp];
#pragma unroll
    for (int mi = 0; mi < 2; mi++)
#pragma unroll
        for (int nd = 0; nd < 2; nd++) {
            int row = wi * 32 + mi * 16 + g;
            int col = h * D_ + wj * 16 + nd * 8 + tg * 2;
            float2 o0 = {accO[mi][nd][0] * inv[mi][0], accO[mi][nd][1] * inv[mi][0]};
            float2 o1 = {accO[mi][nd][2] * inv[mi][1], accO[mi][nd][3] * inv[mi][1]};
            *(float2*)(att + (size_t)((i0 + row) * B_ + b) * E_ + col) = o0;
            *(float2*)(att + (size_t)((i0 + row + 8) * B_ + b) * E_ + col) = o1;
        }
}

// ---------------- launch ----------------
extern "C" void kernel_launch(void* const* d_in, const int* in_sizes, int n_in,
                              void* d_out, int out_size)
{
    (void)in_sizes; (void)n_in; (void)out_size;
    const float* input  = (const float*)d_in[0];
    const float* pos    = (const float*)d_in[1];
    const float* factor = (const float*)d_in[2];
    const float* w_in   = (const float*)d_in[3];
    const float* w_pos  = (const float*)d_in[4];
    const float* w_out  = (const float*)d_in[5];
    const float* bw_in  = (const float*)d_in[6];
    const float* bw_pos = (const float*)d_in[7];
    const float* bw_out = (const float*)d_in[8];
    const float* rwb    = (const float*)d_in[9];
    const float* rrb    = (const float*)d_in[10];

    float *pWin, *pWpos, *pWout, *pbin, *pbpos, *pbout, *prw, *prr,
          *pqkv, *pr, *patt;
    cudaGetSymbolAddress((void**)&pWin,  g_Win);
    cudaGetSymbolAddress((void**)&pWpos, g_Wpos);
    cudaGetSymbolAddress((void**)&pWout, g_Wout);
    cudaGetSymbolAddress((void**)&pbin,  g_bin);
    cudaGetSymbolAddress((void**)&pbpos, g_bpos);
    cudaGetSymbolAddress((void**)&pbout, g_bout);
    cudaGetSymbolAddress((void**)&prw,   g_rw);
    cudaGetSymbolAddress((void**)&prr,   g_rr);
    cudaGetSymbolAddress((void**)&pqkv,  g_qkv);
    cudaGetSymbolAddress((void**)&pr,    g_r);
    cudaGetSymbolAddress((void**)&patt,  g_att);

    cudaFuncSetAttribute(gemm3,      cudaFuncAttributeMaxDynamicSharedMemorySize, GEMM_SMEM);
    cudaFuncSetAttribute(attn_fused, cudaFuncAttributeMaxDynamicSharedMemorySize, ATTN_SMEM);

    // 1) hypernet
    hyper_all<<<(HN7 + 255) / 256, 256>>>(w_in, w_pos, w_out, bw_in, bw_pos, bw_out,
                                          rwb, rrb, factor,
                                          pWin, pWpos, pWout, pbin, pbpos, pbout, prw, prr);

    // 2) projections (3xtf32, register double-buffered)
    gemm3<<<dim3(3 * E_ / 128, TB_ / 128), 256, GEMM_SMEM>>>(input, pWin, pbin, pqkv, TB_, 3 * E_, E_);
    gemm3<<<dim3(E_ / 128, (RB_ + 127) / 128), 256, GEMM_SMEM>>>(pos, pWpos, pbpos, pr, RB_, E_, E_);

    // 3) fused attention (R5-identical)
    attn_fused<<<dim3(T_ / 64, B_ * H_), 256, ATTN_SMEM>>>(pqkv, pr, prw, prr, patt);

    // 4) output projection -> d_out
    gemm3<<<dim3(E_ / 128, TB_ / 128), 256, GEMM_SMEM>>>(patt, pWout, pbout, (float*)d_out, TB_, E_, E_);
}